// round 4
// baseline (speedup 1.0000x reference)
#include <cuda_runtime.h>
#include <math.h>

#define BATCH 32
#define PP 576
#define DD 768
#define KP 17
#define KK 16
#define CC 200

// Output layout (floats), outputs concatenated in reference return order:
// A [32,17,24,24] -> 313344, v_norm [32,16,768] -> 393216,
// logits_parts [32,16,200] -> 102400, logits_agg [32,200] -> 6400
#define A_OFF  0
#define VN_OFF 313344
#define LP_OFF 706560
#define AG_OFF 808960

// Scratch (no allocations allowed)
__device__ float g_psq[KP];
__device__ float g_a[BATCH * PP * KP];     // a in [b][p][k] row-major
__device__ float g_v[BATCH * KK * DD];     // pooled parts (already /P)

// ---------------------------------------------------------------------------
// Kernel 1: p_sq[k] = sum_d proto[k][d]^2
// ---------------------------------------------------------------------------
__global__ void psq_kernel(const float* __restrict__ proto) {
    int k = blockIdx.x;
    int t = threadIdx.x;
    float s = 0.f;
    for (int d = t; d < DD; d += 256) {
        float v = proto[k * DD + d];
        s += v * v;
    }
    __shared__ float red[8];
    for (int o = 16; o > 0; o >>= 1) s += __shfl_xor_sync(0xffffffffu, s, o);
    if ((t & 31) == 0) red[t >> 5] = s;
    __syncthreads();
    if (t == 0) {
        float tot = 0.f;
        #pragma unroll
        for (int w = 0; w < 8; w++) tot += red[w];
        g_psq[k] = tot;
    }
}

// ---------------------------------------------------------------------------
// Kernel 2: assignment. a = softmax_k(2*x.proto_k - p_sq_k)
// Writes A (transposed) to d_out and a (row-major) to g_a.
// Grid: (18, 32), 256 threads. Dynamic smem: prototypes 17*768 floats.
// Each warp processes 4 rows, register-blocked so each LDS.128 of prototype
// feeds 16 FMAs.
// ---------------------------------------------------------------------------
__global__ __launch_bounds__(256, 2) void assign_kernel(
    const float* __restrict__ x, const float* __restrict__ proto,
    float* __restrict__ outA)
{
    extern __shared__ float sp[];  // [KP*DD]
    int t = threadIdx.x;
    for (int i = t; i < KP * DD; i += 256) sp[i] = proto[i];
    __syncthreads();

    int b    = blockIdx.y;
    int warp = t >> 5;
    int lane = t & 31;
    int p0   = blockIdx.x * 32 + warp * 4;
    const float* xb = x + (size_t)b * PP * DD;
    float psq = (lane < KP) ? g_psq[lane] : 0.f;

    float acc[4][KP];
    #pragma unroll
    for (int r = 0; r < 4; r++)
        #pragma unroll
        for (int k = 0; k < KP; k++) acc[r][k] = 0.f;

    #pragma unroll
    for (int j = 0; j < 6; j++) {
        float4 xv[4];
        #pragma unroll
        for (int r = 0; r < 4; r++)
            xv[r] = *(const float4*)(xb + (size_t)(p0 + r) * DD + j * 128 + lane * 4);
        #pragma unroll
        for (int k = 0; k < KP; k++) {
            float4 pv = *(const float4*)(sp + k * DD + j * 128 + lane * 4);
            #pragma unroll
            for (int r = 0; r < 4; r++) {
                acc[r][k] = fmaf(xv[r].x, pv.x, acc[r][k]);
                acc[r][k] = fmaf(xv[r].y, pv.y, acc[r][k]);
                acc[r][k] = fmaf(xv[r].z, pv.z, acc[r][k]);
                acc[r][k] = fmaf(xv[r].w, pv.w, acc[r][k]);
            }
        }
    }

    #pragma unroll
    for (int r = 0; r < 4; r++) {
        float srow = 0.f;
        #pragma unroll
        for (int k = 0; k < KP; k++) {
            float v = acc[r][k];
            for (int o = 16; o > 0; o >>= 1) v += __shfl_xor_sync(0xffffffffu, v, o);
            if (lane == k) srow = v;
        }
        // softmax across lanes 0..16
        float s = (lane < KP) ? (2.f * srow - psq) : -1e30f;
        float m = s;
        for (int o = 16; o > 0; o >>= 1) m = fmaxf(m, __shfl_xor_sync(0xffffffffu, m, o));
        float e = (lane < KP) ? expf(s - m) : 0.f;
        float sum = e;
        for (int o = 16; o > 0; o >>= 1) sum += __shfl_xor_sync(0xffffffffu, sum, o);
        float a = e / sum;

        int p = p0 + r;
        if (lane < KP) {
            outA[((size_t)b * KP + lane) * PP + p] = a;
            g_a[((size_t)b * PP + p) * KP + lane] = a;
        }
    }
}

// ---------------------------------------------------------------------------
// Kernel 3: v[b,k,d] = (1/P) * sum_p a[b,p,k] * x[b,p,d]   (k < 16 only)
// Grid: (6, 32), 128 threads. Full a[b] tile (39 KB) in smem.
// Double-buffered x column loads (8-deep MLP).
// ---------------------------------------------------------------------------
__global__ __launch_bounds__(128) void vagg_kernel(const float* __restrict__ x)
{
    __shared__ float sa[PP * KP];  // 39168 B
    int b = blockIdx.y;
    int d = blockIdx.x * 128 + threadIdx.x;
    const float* ab = g_a + (size_t)b * PP * KP;
    for (int i = threadIdx.x; i < PP * KP; i += 128) sa[i] = ab[i];
    __syncthreads();

    const float* xb = x + (size_t)b * PP * DD + d;
    float acc[KK];
    #pragma unroll
    for (int k = 0; k < KK; k++) acc[k] = 0.f;

    float xv[8];
    #pragma unroll
    for (int u = 0; u < 8; u++) xv[u] = __ldg(xb + (size_t)u * DD);

    for (int pg = 0; pg < PP; pg += 8) {
        float xn[8];
        if (pg + 8 < PP) {
            #pragma unroll
            for (int u = 0; u < 8; u++) xn[u] = __ldg(xb + (size_t)(pg + 8 + u) * DD);
        }
        #pragma unroll
        for (int u = 0; u < 8; u++) {
            float xu = xv[u];
            const float* ar = &sa[(pg + u) * KP];
            #pragma unroll
            for (int k = 0; k < KK; k++) acc[k] = fmaf(ar[k], xu, acc[k]);
        }
        #pragma unroll
        for (int u = 0; u < 8; u++) xv[u] = xn[u];
    }

    const float inv = 1.0f / (float)PP;
    #pragma unroll
    for (int k = 0; k < KK; k++)
        g_v[((size_t)b * KK + k) * DD + d] = acc[k] * inv;
}

// ---------------------------------------------------------------------------
// Kernel 4: LayerNorm per (b,k) row of 768. Grid 512, 256 threads.
// ---------------------------------------------------------------------------
__global__ __launch_bounds__(256) void ln_kernel(
    const float* __restrict__ gamma, const float* __restrict__ beta,
    float* __restrict__ vnorm)
{
    int bk = blockIdx.x;
    const float* v = g_v + (size_t)bk * DD;
    int t = threadIdx.x;
    float x0 = v[t], x1 = v[t + 256], x2 = v[t + 512];

    __shared__ float red[8];
    float s = x0 + x1 + x2;
    for (int o = 16; o > 0; o >>= 1) s += __shfl_xor_sync(0xffffffffu, s, o);
    if ((t & 31) == 0) red[t >> 5] = s;
    __syncthreads();
    float tot = 0.f;
    #pragma unroll
    for (int w = 0; w < 8; w++) tot += red[w];
    float mu = tot * (1.f / (float)DD);

    float d0 = x0 - mu, d1 = x1 - mu, d2 = x2 - mu;
    float s2 = d0 * d0 + d1 * d1 + d2 * d2;
    __syncthreads();
    for (int o = 16; o > 0; o >>= 1) s2 += __shfl_xor_sync(0xffffffffu, s2, o);
    if ((t & 31) == 0) red[t >> 5] = s2;
    __syncthreads();
    float tot2 = 0.f;
    #pragma unroll
    for (int w = 0; w < 8; w++) tot2 += red[w];
    float var = tot2 * (1.f / (float)DD);
    float inv = rsqrtf(var + 1e-6f);

    float* o = vnorm + (size_t)bk * DD;
    o[t]       = d0 * inv * gamma[t]       + beta[t];
    o[t + 256] = d1 * inv * gamma[t + 256] + beta[t + 256];
    o[t + 512] = d2 * inv * gamma[t + 512] + beta[t + 512];
}

// ---------------------------------------------------------------------------
// Kernel 5: logits_parts[b,k,c] = v_norm[b,k,:] . w_cls[:,c] + b_cls[c]
// Grid: (4, 32) — each block does 4 k's for one b. 256 threads, c = tid.
// ---------------------------------------------------------------------------
__global__ __launch_bounds__(256) void logits_kernel(
    const float* __restrict__ vnorm, const float* __restrict__ w,
    const float* __restrict__ bias, float* __restrict__ lp)
{
    int b = blockIdx.y, kg = blockIdx.x;
    __shared__ float sv[4 * DD];
    int t = threadIdx.x;
    const float* vb = vnorm + ((size_t)b * KK + kg * 4) * DD;
    for (int i = t; i < 4 * DD; i += 256) sv[i] = vb[i];
    __syncthreads();

    if (t < CC) {
        float acc0 = 0.f, acc1 = 0.f, acc2 = 0.f, acc3 = 0.f;
        #pragma unroll 4
        for (int d = 0; d < DD; d++) {
            float wv = __ldg(w + (size_t)d * CC + t);
            acc0 = fmaf(sv[0 * DD + d], wv, acc0);
            acc1 = fmaf(sv[1 * DD + d], wv, acc1);
            acc2 = fmaf(sv[2 * DD + d], wv, acc2);
            acc3 = fmaf(sv[3 * DD + d], wv, acc3);
        }
        float bb = bias[t];
        float* o = lp + ((size_t)b * KK + kg * 4) * CC + t;
        o[0 * CC] = acc0 + bb;
        o[1 * CC] = acc1 + bb;
        o[2 * CC] = acc2 + bb;
        o[3 * CC] = acc3 + bb;
    }
}

// ---------------------------------------------------------------------------
// Kernel 6: logits_agg[b,c] = mean_k logits_parts[b,k,c]
// ---------------------------------------------------------------------------
__global__ void agg_kernel(const float* __restrict__ lp, float* __restrict__ agg)
{
    int i = blockIdx.x * 256 + threadIdx.x;
    if (i < BATCH * CC) {
        int b = i / CC, c = i % CC;
        const float* base = lp + (size_t)b * KK * CC + c;
        float s = 0.f;
        #pragma unroll
        for (int k = 0; k < KK; k++) s += base[k * CC];
        agg[i] = s * (1.f / (float)KK);
    }
}

// ---------------------------------------------------------------------------
extern "C" void kernel_launch(void* const* d_in, const int* in_sizes, int n_in,
                              void* d_out, int out_size)
{
    const float* x      = (const float*)d_in[0];  // [32,24,24,768]
    const float* proto  = (const float*)d_in[1];  // [17,768]
    const float* gamma  = (const float*)d_in[2];  // [768]
    const float* beta   = (const float*)d_in[3];  // [768]
    const float* w_cls  = (const float*)d_in[4];  // [768,200]
    const float* b_cls  = (const float*)d_in[5];  // [200]
    float* out = (float*)d_out;

    // 52224 B dynamic smem for prototypes in assign_kernel
    cudaFuncSetAttribute(assign_kernel,
                         cudaFuncAttributeMaxDynamicSharedMemorySize,
                         KP * DD * (int)sizeof(float));

    psq_kernel<<<KP, 256>>>(proto);

    dim3 g2(PP / 32, BATCH);
    assign_kernel<<<g2, 256, KP * DD * sizeof(float)>>>(x, proto, out + A_OFF);

    dim3 g3(DD / 128, BATCH);
    vagg_kernel<<<g3, 128>>>(x);

    ln_kernel<<<BATCH * KK, 256>>>(gamma, beta, out + VN_OFF);

    dim3 g5(KK / 4, BATCH);
    logits_kernel<<<g5, 256>>>(out + VN_OFF, w_cls, b_cls, out + LP_OFF);

    agg_kernel<<<(BATCH * CC + 255) / 256, 256>>>(out + LP_OFF, out + AG_OFF);
}

// round 6
// speedup vs baseline: 1.2406x; 1.2406x over previous
#include <cuda_runtime.h>
#include <math.h>

#define BATCH 32
#define PP 576
#define DD 768
#define KP 17
#define KK 16
#define CC 200
#define ASTRIDE 20   // padded k-stride for a scratch (80B, 16B-aligned rows)

// Output layout (floats), concatenated in reference return order:
// A [32,17,24,24], v_norm [32,16,768], logits_parts [32,16,200], logits_agg [32,200]
#define A_OFF  0
#define VN_OFF 313344
#define LP_OFF 706560
#define AG_OFF 808960

// Scratch (no allocations allowed)
__device__ float g_psq[KP];
__device__ float g_a[BATCH * PP * ASTRIDE];      // a, [b][p][20] (k in 0..16)
__device__ float g_vp[4][BATCH * KK * DD];       // partial pooled parts (4 p-chunks)

// ---------------- packed f32x2 helpers ----------------
__device__ __forceinline__ void fma2(unsigned long long& acc,
                                     unsigned long long a,
                                     unsigned long long b) {
    asm("fma.rn.f32x2 %0, %1, %2, %0;" : "+l"(acc) : "l"(a), "l"(b));
}
__device__ __forceinline__ unsigned long long pack2(float lo, float hi) {
    unsigned long long r;
    asm("mov.b64 %0, {%1, %2};" : "=l"(r) : "f"(lo), "f"(hi));
    return r;
}
__device__ __forceinline__ float2 unpack2(unsigned long long v) {
    float2 r;
    asm("mov.b64 {%0, %1}, %2;" : "=f"(r.x), "=f"(r.y) : "l"(v));
    return r;
}

// ---------------------------------------------------------------------------
// Kernel 1: p_sq[k] = sum_d proto[k][d]^2
// ---------------------------------------------------------------------------
__global__ void psq_kernel(const float* __restrict__ proto) {
    int k = blockIdx.x;
    int t = threadIdx.x;
    float s = 0.f;
    for (int d = t; d < DD; d += 256) {
        float v = proto[k * DD + d];
        s += v * v;
    }
    __shared__ float red[8];
    for (int o = 16; o > 0; o >>= 1) s += __shfl_xor_sync(0xffffffffu, s, o);
    if ((t & 31) == 0) red[t >> 5] = s;
    __syncthreads();
    if (t == 0) {
        float tot = 0.f;
        #pragma unroll
        for (int w = 0; w < 8; w++) tot += red[w];
        g_psq[k] = tot;
    }
}

// ---------------------------------------------------------------------------
// Kernel 2: assignment. a = softmax_k(2*x.proto_k - p_sq_k)
// Packed f32x2 FMA. Each warp processes 2 rows; 8 warps -> 16 rows/block.
// Grid (36, 32). Dynamic smem: prototypes (52 KB).
// ---------------------------------------------------------------------------
__global__ __launch_bounds__(256, 2) void assign_kernel(
    const float* __restrict__ x, const float* __restrict__ proto,
    float* __restrict__ outA)
{
    extern __shared__ float sp[];  // [KP*DD]
    int t = threadIdx.x;
    for (int i = t; i < KP * DD; i += 256) sp[i] = proto[i];
    __syncthreads();

    int b    = blockIdx.y;
    int warp = t >> 5;
    int lane = t & 31;
    int p0   = blockIdx.x * 16 + warp * 2;
    const float* xb = x + (size_t)b * PP * DD;
    float psq = (lane < KP) ? g_psq[lane] : 0.f;

    unsigned long long acc[2][KP];
    #pragma unroll
    for (int r = 0; r < 2; r++)
        #pragma unroll
        for (int k = 0; k < KP; k++) acc[r][k] = 0ull;

    #pragma unroll
    for (int j = 0; j < 6; j++) {
        ulonglong2 xq[2];
        #pragma unroll
        for (int r = 0; r < 2; r++)
            xq[r] = *(const ulonglong2*)(xb + (size_t)(p0 + r) * DD + j * 128 + lane * 4);
        #pragma unroll
        for (int k = 0; k < KP; k++) {
            ulonglong2 pv = *(const ulonglong2*)(sp + k * DD + j * 128 + lane * 4);
            #pragma unroll
            for (int r = 0; r < 2; r++) {
                fma2(acc[r][k], xq[r].x, pv.x);
                fma2(acc[r][k], xq[r].y, pv.y);
            }
        }
    }

    #pragma unroll
    for (int r = 0; r < 2; r++) {
        float srow = 0.f;
        #pragma unroll
        for (int k = 0; k < KP; k++) {
            float2 h = unpack2(acc[r][k]);
            float v = h.x + h.y;
            for (int o = 16; o > 0; o >>= 1) v += __shfl_xor_sync(0xffffffffu, v, o);
            if (lane == k) srow = v;
        }
        float s = (lane < KP) ? (2.f * srow - psq) : -1e30f;
        float m = s;
        for (int o = 16; o > 0; o >>= 1) m = fmaxf(m, __shfl_xor_sync(0xffffffffu, m, o));
        float e = (lane < KP) ? expf(s - m) : 0.f;
        float sum = e;
        for (int o = 16; o > 0; o >>= 1) sum += __shfl_xor_sync(0xffffffffu, sum, o);
        float a = e / sum;

        int p = p0 + r;
        if (lane < KP) {
            outA[((size_t)b * KP + lane) * PP + p] = a;
            g_a[((size_t)b * PP + p) * ASTRIDE + lane] = a;
        }
    }
}

// ---------------------------------------------------------------------------
// Kernel 3: partial v[b,k,d] = sum_{p in chunk} a[b,p,k] * x[b,p,d]
// Grid (6 d-tiles, 4 p-chunks, 32 b), 128 threads. a tile 11.5 KB in smem.
// Packed FMA on (k,k+1) pairs; 4x LDS.128 (broadcast) + 1 pack + 8 FFMA2 per p.
// ---------------------------------------------------------------------------
__global__ __launch_bounds__(128) void vagg_kernel(const float* __restrict__ x)
{
    __shared__ float sa[144 * ASTRIDE];
    int b = blockIdx.z, chunk = blockIdx.y;
    int d = blockIdx.x * 128 + threadIdx.x;
    int p0 = chunk * 144;

    const float4* src = (const float4*)(g_a + ((size_t)b * PP + p0) * ASTRIDE);
    float4* dst = (float4*)sa;
    for (int i = threadIdx.x; i < 144 * ASTRIDE / 4; i += 128) dst[i] = src[i];
    __syncthreads();

    const float* xb = x + ((size_t)b * PP + p0) * DD + d;

    unsigned long long acc[8];
    #pragma unroll
    for (int j = 0; j < 8; j++) acc[j] = 0ull;

    float xv[8];
    #pragma unroll
    for (int u = 0; u < 8; u++) xv[u] = __ldg(xb + (size_t)u * DD);

    for (int pg = 0; pg < 144; pg += 8) {
        float xn[8];
        if (pg + 8 < 144) {
            #pragma unroll
            for (int u = 0; u < 8; u++) xn[u] = __ldg(xb + (size_t)(pg + 8 + u) * DD);
        }
        #pragma unroll
        for (int u = 0; u < 8; u++) {
            const ulonglong2* ar = (const ulonglong2*)&sa[(pg + u) * ASTRIDE];
            ulonglong2 q0 = ar[0], q1 = ar[1];
            unsigned long long xx = pack2(xv[u], xv[u]);
            fma2(acc[0], q0.x, xx);
            fma2(acc[1], q0.y, xx);
            fma2(acc[2], q1.x, xx);
            fma2(acc[3], q1.y, xx);
            ulonglong2 q2 = ar[2], q3 = ar[3];
            fma2(acc[4], q2.x, xx);
            fma2(acc[5], q2.y, xx);
            fma2(acc[6], q3.x, xx);
            fma2(acc[7], q3.y, xx);
        }
        #pragma unroll
        for (int u = 0; u < 8; u++) xv[u] = xn[u];
    }

    float* vp = g_vp[chunk] + (size_t)b * KK * DD + d;
    #pragma unroll
    for (int j = 0; j < 8; j++) {
        float2 o = unpack2(acc[j]);
        vp[(2 * j) * DD]     = o.x;
        vp[(2 * j + 1) * DD] = o.y;
    }
}

// ---------------------------------------------------------------------------
// Kernel 4: sum partials, /P, LayerNorm per (b,k). Grid 512, 256 threads.
// ---------------------------------------------------------------------------
__global__ __launch_bounds__(256) void ln_kernel(
    const float* __restrict__ gamma, const float* __restrict__ beta,
    float* __restrict__ vnorm)
{
    int bk = blockIdx.x;
    size_t base = (size_t)bk * DD;
    int t = threadIdx.x;
    const float invP = 1.0f / (float)PP;

    float x0 = (g_vp[0][base + t]       + g_vp[1][base + t]
              + g_vp[2][base + t]       + g_vp[3][base + t]) * invP;
    float x1 = (g_vp[0][base + t + 256] + g_vp[1][base + t + 256]
              + g_vp[2][base + t + 256] + g_vp[3][base + t + 256]) * invP;
    float x2 = (g_vp[0][base + t + 512] + g_vp[1][base + t + 512]
              + g_vp[2][base + t + 512] + g_vp[3][base + t + 512]) * invP;

    __shared__ float red[8];
    float s = x0 + x1 + x2;
    for (int o = 16; o > 0; o >>= 1) s += __shfl_xor_sync(0xffffffffu, s, o);
    if ((t & 31) == 0) red[t >> 5] = s;
    __syncthreads();
    float tot = 0.f;
    #pragma unroll
    for (int w = 0; w < 8; w++) tot += red[w];
    float mu = tot * (1.f / (float)DD);

    float d0 = x0 - mu, d1 = x1 - mu, d2 = x2 - mu;
    float s2 = d0 * d0 + d1 * d1 + d2 * d2;
    __syncthreads();
    for (int o = 16; o > 0; o >>= 1) s2 += __shfl_xor_sync(0xffffffffu, s2, o);
    if ((t & 31) == 0) red[t >> 5] = s2;
    __syncthreads();
    float tot2 = 0.f;
    #pragma unroll
    for (int w = 0; w < 8; w++) tot2 += red[w];
    float var = tot2 * (1.f / (float)DD);
    float inv = rsqrtf(var + 1e-6f);

    float* o = vnorm + base;
    o[t]       = d0 * inv * gamma[t]       + beta[t];
    o[t + 256] = d1 * inv * gamma[t + 256] + beta[t + 256];
    o[t + 512] = d2 * inv * gamma[t + 512] + beta[t + 512];
}

// ---------------------------------------------------------------------------
// Kernel 5: logits_parts[b,k,c] = v_norm[b,k,:] . w_cls[:,c] + b_cls[c]
// Grid (2 k-groups, 2 c-halves, 32 b), 128 threads (100 active per block).
// sv staged d-major [d][8k]; broadcast LDS.128 + packed FMA on k-pairs.
// ---------------------------------------------------------------------------
__global__ __launch_bounds__(128) void logits_kernel(
    const float* __restrict__ vnorm, const float* __restrict__ w,
    const float* __restrict__ bias, float* __restrict__ lp)
{
    __shared__ float sv[DD * 8];
    int b = blockIdx.z, kg = blockIdx.x, ch = blockIdx.y;
    int t = threadIdx.x;
    const float* vb = vnorm + ((size_t)b * KK + kg * 8) * DD;
    for (int i = t; i < 8 * DD; i += 128) {
        int kk = i / DD;
        int d  = i - kk * DD;
        sv[d * 8 + kk] = vb[i];
    }
    __syncthreads();

    if (t < 100) {
        int c = ch * 100 + t;
        unsigned long long acc[4];
        #pragma unroll
        for (int j = 0; j < 4; j++) acc[j] = 0ull;

        float wv[8];
        #pragma unroll
        for (int u = 0; u < 8; u++) wv[u] = __ldg(w + (size_t)u * CC + c);

        for (int dg = 0; dg < DD; dg += 8) {
            float wn[8];
            if (dg + 8 < DD) {
                #pragma unroll
                for (int u = 0; u < 8; u++) wn[u] = __ldg(w + (size_t)(dg + 8 + u) * CC + c);
            }
            #pragma unroll
            for (int u = 0; u < 8; u++) {
                const ulonglong2* sp2 = (const ulonglong2*)&sv[(dg + u) * 8];
                ulonglong2 q0 = sp2[0], q1 = sp2[1];
                unsigned long long ww = pack2(wv[u], wv[u]);
                fma2(acc[0], q0.x, ww);
                fma2(acc[1], q0.y, ww);
                fma2(acc[2], q1.x, ww);
                fma2(acc[3], q1.y, ww);
            }
            #pragma unroll
            for (int u = 0; u < 8; u++) wv[u] = wn[u];
        }

        float bb = bias[c];
        float* o = lp + ((size_t)b * KK + kg * 8) * CC + c;
        #pragma unroll
        for (int j = 0; j < 4; j++) {
            float2 r = unpack2(acc[j]);
            o[(2 * j) * CC]     = r.x + bb;
            o[(2 * j + 1) * CC] = r.y + bb;
        }
    }
}

// ---------------------------------------------------------------------------
// Kernel 6: logits_agg[b,c] = mean_k logits_parts[b,k,c]
// ---------------------------------------------------------------------------
__global__ void agg_kernel(const float* __restrict__ lp, float* __restrict__ agg)
{
    int i = blockIdx.x * 256 + threadIdx.x;
    if (i < BATCH * CC) {
        int b = i / CC, c = i % CC;
        const float* base = lp + (size_t)b * KK * CC + c;
        float s = 0.f;
        #pragma unroll
        for (int k = 0; k < KK; k++) s += base[k * CC];
        agg[i] = s * (1.f / (float)KK);
    }
}

// ---------------------------------------------------------------------------
extern "C" void kernel_launch(void* const* d_in, const int* in_sizes, int n_in,
                              void* d_out, int out_size)
{
    const float* x      = (const float*)d_in[0];  // [32,24,24,768]
    const float* proto  = (const float*)d_in[1];  // [17,768]
    const float* gamma  = (const float*)d_in[2];  // [768]
    const float* beta   = (const float*)d_in[3];  // [768]
    const float* w_cls  = (const float*)d_in[4];  // [768,200]
    const float* b_cls  = (const float*)d_in[5];  // [200]
    float* out = (float*)d_out;

    cudaFuncSetAttribute(assign_kernel,
                         cudaFuncAttributeMaxDynamicSharedMemorySize,
                         KP * DD * (int)sizeof(float));

    psq_kernel<<<KP, 256>>>(proto);

    dim3 g2(PP / 16, BATCH);
    assign_kernel<<<g2, 256, KP * DD * sizeof(float)>>>(x, proto, out + A_OFF);

    dim3 g3(DD / 128, 4, BATCH);
    vagg_kernel<<<g3, 128>>>(x);

    ln_kernel<<<BATCH * KK, 256>>>(gamma, beta, out + VN_OFF);

    dim3 g5(2, 2, BATCH);
    logits_kernel<<<g5, 128>>>(out + VN_OFF, w_cls, b_cls, out + LP_OFF);

    agg_kernel<<<(BATCH * CC + 255) / 256, 256>>>(out + LP_OFF, out + AG_OFF);
}